// round 8
// baseline (speedup 1.0000x reference)
#include <cuda_runtime.h>

// Path signature, depth 3. path: (32, 128, 48) fp32. Out: 32 x 112944.
//
// S3[i,j,k] = sum_t w[i][t][j] * v[t][k]
//   v[t][j]    = path[t+1][j] - path[t][j]
//   w[i][t][j] = S2prev[i][j] + (0.5*S1prev[i] + v[t][i]/6) * v[t][j]
//   S2[i][j]  += (S1prev[i] + 0.5*v[t][i]) * v[t][j]
//
// Block (bx,b): two i-planes {2bx, 2bx+1}, full 48x48 k-range, 192 threads.
// Thread grid 24(j-pairs) x 8(k): per-thread 2j x 6k x 2 planes = 12 u64
// accumulators, packed fma.rn.f32x2 along j. v stored PRE-DUPLICATED
// (float2{v,v}) so phase B needs no dup movs. Producers (threads 0..95)
// are pipelined one chunk ahead of consumers; double-buffered shared,
// one barrier per stage. Extra consumer warps (vs 144-thr version) raise
// resident warps/SM ~33% with no extra producer work.

#define NB     32
#define LPATH  128
#define C      48
#define NSTEPS (LPATH - 1)          // 127
#define LVL2   (C * C)
#define LVL3   (C * C * C)
#define STR    (C + LVL2 + LVL3)    // 112944
#define OFF2   C
#define OFF3   (C + LVL2)
#define TCH    8
#define NFULL  15
#define TAILT  (NSTEPS - NFULL * TCH)   // 7

typedef unsigned long long u64;

__device__ __forceinline__ void ffma2(u64& d, u64 a, u64 b) {
    asm("fma.rn.f32x2 %0, %1, %2, %0;" : "+l"(d) : "l"(a), "l"(b));
}
__device__ __forceinline__ float2 unpk(u64 a) {
    float2 r;
    asm("mov.b64 {%0, %1}, %2;" : "=f"(r.x), "=f"(r.y) : "l"(a));
    return r;
}

// Phase A: producer thread (tid < 96) computes w rows for its plane and the
// pre-duplicated v (group r==0 only).
template<int T>
__device__ __forceinline__ void phase_a(
    const float* __restrict__ pb, int base_t, int buf, int i_r, int r, int jj,
    float& p_j, float& p_i, float p0_i, float& S2,
    float2 (*sh_vd)[TCH][C], float (*sh_w)[2][TCH][C])
{
#pragma unroll
    for (int t = 0; t < T; ++t) {
        const float pn_j = pb[(base_t + t + 1) * C + jj];  // coalesced
        const float pn_i = pb[(base_t + t + 1) * C + i_r]; // broadcast
        const float v_j = pn_j - p_j;
        const float v_i = pn_i - p_i;
        const float s1  = p_i - p0_i;
        if (r == 0) sh_vd[buf][t][jj] = make_float2(v_j, v_j);
        sh_w[buf][r][t][jj] = fmaf(fmaf(1.0f / 6.0f, v_i, 0.5f * s1), v_j, S2);
        S2 = fmaf(fmaf(0.5f, v_i, s1), v_j, S2);
        p_j = pn_j;
        p_i = pn_i;
    }
}

// Phase B: all 192 threads. acc[plane][kx]: f32x2 pair = rows (j0, j0+1),
// column k0+kx, kx in [0,6).
template<int T>
__device__ __forceinline__ void phase_b(
    int buf, int j0, int k0, u64 (&acc0)[6], u64 (&acc1)[6],
    float2 (*sh_vd)[TCH][C], float (*sh_w)[2][TCH][C])
{
#pragma unroll 2
    for (int t = 0; t < T; ++t) {
        u64 wa, wb;
        // j-pair loads (8B, aligned: j0 even)
        wa = *(const u64*)&sh_w[buf][0][t][j0];
        wb = *(const u64*)&sh_w[buf][1][t][j0];
        // six duplicated v values: three 16B loads (k0 even -> aligned)
        const ulonglong2 v01 = *(const ulonglong2*)&sh_vd[buf][t][k0];
        const ulonglong2 v23 = *(const ulonglong2*)&sh_vd[buf][t][k0 + 2];
        const ulonglong2 v45 = *(const ulonglong2*)&sh_vd[buf][t][k0 + 4];
        const u64 vp[6] = { v01.x, v01.y, v23.x, v23.y, v45.x, v45.y };
#pragma unroll
        for (int kx = 0; kx < 6; ++kx) {
            ffma2(acc0[kx], wa, vp[kx]);
            ffma2(acc1[kx], wb, vp[kx]);
        }
    }
}

__global__ __launch_bounds__(192, 6)
void sig_depth3_kernel(const float* __restrict__ path, float* __restrict__ out)
{
    const int bx  = blockIdx.x;   // 0..23 -> i0 = 2bx, i1 = 2bx+1
    const int b   = blockIdx.y;   // 0..31
    const int tid = threadIdx.x;  // 0..191

    __shared__ __align__(16) float2 sh_vd[2][TCH][C];
    __shared__ __align__(16) float  sh_w[2][2][TCH][C];

    const float* pb = path + (size_t)b * LPATH * C;

    u64 acc0[6], acc1[6];
#pragma unroll
    for (int kx = 0; kx < 6; ++kx) { acc0[kx] = 0ull; acc1[kx] = 0ull; }

    const int j0 = (tid / 8) * 2;   // 0,2,..,46 (j-pair base)
    const int k0 = (tid % 8) * 6;   // 0,6,..,42

    const bool prod = (tid < 2 * C);
    const int r   = (tid < C) ? 0 : 1;
    const int jj  = prod ? (tid - r * C) : 0;
    const int i_r = 2 * bx + r;

    float p_j = 0.0f, p_i = 0.0f, p0_i = 0.0f, S2 = 0.0f;
    if (prod) {
        p_j  = pb[jj];
        p0_i = pb[i_r];
        p_i  = p0_i;
    }

    // ---- Pipelined mainloop: A(s+1) before B(s), one barrier per stage ----
    if (prod) phase_a<TCH>(pb, 0, 0, i_r, r, jj, p_j, p_i, p0_i, S2,
                           sh_vd, sh_w);
    __syncthreads();

#pragma unroll 1
    for (int s = 0; s < NFULL - 1; ++s) {     // s = 0..13
        if (prod) phase_a<TCH>(pb, (s + 1) * TCH, (s + 1) & 1, i_r, r, jj,
                               p_j, p_i, p0_i, S2, sh_vd, sh_w);
        phase_b<TCH>(s & 1, j0, k0, acc0, acc1, sh_vd, sh_w);
        __syncthreads();
    }
    if (prod) phase_a<TAILT>(pb, NFULL * TCH, NFULL & 1, i_r, r, jj,
                             p_j, p_i, p0_i, S2, sh_vd, sh_w);
    phase_b<TCH>((NFULL - 1) & 1, j0, k0, acc0, acc1, sh_vd, sh_w);
    __syncthreads();
    phase_b<TAILT>(NFULL & 1, j0, k0, acc0, acc1, sh_vd, sh_w);

    // ---- Epilogue ----
    float* ob = out + (size_t)b * STR;

    float* o30 = ob + OFF3 + (size_t)(2 * bx)     * LVL2;
    float* o31 = ob + OFF3 + (size_t)(2 * bx + 1) * LVL2;
    {
        // Unpack: acc[kx] holds (row j0, row j0+1) at column k0+kx.
        float lo0[6], hi0[6], lo1[6], hi1[6];
#pragma unroll
        for (int kx = 0; kx < 6; ++kx) {
            const float2 a = unpk(acc0[kx]); lo0[kx] = a.x; hi0[kx] = a.y;
            const float2 c = unpk(acc1[kx]); lo1[kx] = c.x; hi1[kx] = c.y;
        }
        const int jlo = j0, jhi = j0 + 1;
#pragma unroll
        for (int kp = 0; kp < 3; ++kp) {   // float2 stores (8B aligned)
            *(float2*)&o30[jlo * C + k0 + 2 * kp] = make_float2(lo0[2*kp], lo0[2*kp+1]);
            *(float2*)&o30[jhi * C + k0 + 2 * kp] = make_float2(hi0[2*kp], hi0[2*kp+1]);
            *(float2*)&o31[jlo * C + k0 + 2 * kp] = make_float2(lo1[2*kp], lo1[2*kp+1]);
            *(float2*)&o31[jhi * C + k0 + 2 * kp] = make_float2(hi1[2*kp], hi1[2*kp+1]);
        }
    }

    if (prod) {
        ob[OFF2 + i_r * C + jj] = S2;            // level 2, rows i0/i1
        if (bx == 0 && r == 0) {
            // p_j now holds path[b][127][jj]
            ob[jj] = p_j - pb[jj];               // level 1
        }
    }
}

extern "C" void kernel_launch(void* const* d_in, const int* in_sizes, int n_in,
                              void* d_out, int out_size)
{
    (void)in_sizes; (void)n_in; (void)out_size;
    const float* path = (const float*)d_in[0];
    float* out = (float*)d_out;
    dim3 grid(C / 2, NB);   // (i-pairs, batch) = (24, 32)
    dim3 block(192);
    sig_depth3_kernel<<<grid, block>>>(path, out);
}

// round 9
// speedup vs baseline: 1.1683x; 1.1683x over previous
#include <cuda_runtime.h>

// Path signature, depth 3 — TWO-KERNEL split. path: (32,128,48) fp32.
// Out per batch: [lvl1 48 | lvl2 2304 | lvl3 110592] = 112944.
//
// Kernel 1 (phase A): for each (b,i,j) runs the serial S2 recurrence over
// t and writes w[b,i,t,j] (+ v[b,t,j]) to device scratch; emits lvl1/lvl2.
// Kernel 2 (phase B): barrier-free batched outer-product accumulation
//   S3[b,i,j,k] = sum_t w[b,i,t,j] * v[b,t,k]
// Block (bx,b): planes i0=2bx,i1=2bx+1; 96 threads = 12(j)x8(k); per-thread
// tile 4j x 6k x 2 planes, packed fma.rn.f32x2 along j (w j-pairs come free
// from LDG.128; v duplicated via mov.b64). No shared memory, no syncs.

#define NB     32
#define LPATH  128
#define C      48
#define NSTEPS (LPATH - 1)          // 127
#define LVL2   (C * C)
#define STR    (C + LVL2 + C * C * C)   // 112944
#define OFF2   C
#define OFF3   (C + LVL2)

typedef unsigned long long u64;

// Scratch (static device arrays — allocation-free).
__device__ __align__(256) float g_w[(size_t)NB * C * NSTEPS * C];  // [b][i][t][j] 37.5MB
__device__ __align__(256) float g_v[(size_t)NB * NSTEPS * C];      // [b][t][k]    0.78MB

__device__ __forceinline__ void ffma2(u64& d, u64 a, u64 b) {
    asm("fma.rn.f32x2 %0, %1, %2, %0;" : "+l"(d) : "l"(a), "l"(b));
}
__device__ __forceinline__ u64 dup_f32(float x) {
    u64 r;
    asm("mov.b64 %0, {%1, %1};" : "=l"(r) : "f"(x));
    return r;
}
__device__ __forceinline__ float2 unpk(u64 a) {
    float2 r;
    asm("mov.b64 {%0, %1}, %2;" : "=f"(r.x), "=f"(r.y) : "l"(a));
    return r;
}

// ---------------- Kernel 1: phase A ----------------
// block (48, 8): tx = j, ty = local i; grid (6, 32).
__global__ __launch_bounds__(384)
void sig_phase_a(const float* __restrict__ path, float* __restrict__ out)
{
    const int j  = threadIdx.x;               // 0..47
    const int i  = blockIdx.x * 8 + threadIdx.y;  // 0..47
    const int b  = blockIdx.y;

    const float* pb = path + (size_t)b * LPATH * C;

    float p_j  = pb[j];
    float p0_i = pb[i];
    float p_i  = p0_i;
    float S2   = 0.0f;

    float* wrow = g_w + ((size_t)(b * C + i) * NSTEPS) * C + j;
    float* vrow = g_v + (size_t)b * NSTEPS * C + j;
    const bool wv = (i == 0);

#pragma unroll 4
    for (int t = 0; t < NSTEPS; ++t) {
        const float pn_j = pb[(t + 1) * C + j];   // coalesced (L1-hot)
        const float pn_i = pb[(t + 1) * C + i];   // broadcast
        const float v_j = pn_j - p_j;
        const float v_i = pn_i - p_i;
        const float s1  = p_i - p0_i;
        wrow[(size_t)t * C] = fmaf(fmaf(1.0f / 6.0f, v_i, 0.5f * s1), v_j, S2);
        if (wv) vrow[(size_t)t * C] = v_j;
        S2 = fmaf(fmaf(0.5f, v_i, s1), v_j, S2);
        p_j = pn_j;
        p_i = pn_i;
    }

    float* ob = out + (size_t)b * STR;
    ob[OFF2 + i * C + j] = S2;                 // level 2
    if (wv) ob[j] = p_j - pb[j];               // level 1 (p_j = path[127][j])
}

// ---------------- Kernel 2: phase B (barrier-free) ----------------
__global__ __launch_bounds__(96, 5)
void sig_phase_b(float* __restrict__ out)
{
    const int bx  = blockIdx.x;   // 0..23 -> i0=2bx, i1=2bx+1
    const int b   = blockIdx.y;   // 0..31
    const int tid = threadIdx.x;  // 0..95

    const int jg = tid / 8;       // 0..11
    const int kg = tid % 8;       // 0..7
    const int j0 = jg * 4;        // 16B-aligned into 192B rows
    const int k0 = kg * 6;        // 8B-aligned

    const int i0 = 2 * bx, i1 = i0 + 1;
    const float* w0p = g_w + ((size_t)(b * C + i0) * NSTEPS) * C + j0;
    const float* w1p = g_w + ((size_t)(b * C + i1) * NSTEPS) * C + j0;
    const float* vp  = g_v + (size_t)b * NSTEPS * C + k0;

    // acc[plane][jp][kx]: f32x2 pair = rows (j0+2jp, j0+2jp+1), col k0+kx
    u64 acc0[2][6], acc1[2][6];
#pragma unroll
    for (int jp = 0; jp < 2; ++jp)
#pragma unroll
        for (int kx = 0; kx < 6; ++kx) { acc0[jp][kx] = 0ull; acc1[jp][kx] = 0ull; }

#pragma unroll 4
    for (int t = 0; t < NSTEPS; ++t) {
        const ulonglong2 W0 = *(const ulonglong2*)(w0p + (size_t)t * C); // LDG.128
        const ulonglong2 W1 = *(const ulonglong2*)(w1p + (size_t)t * C);
        const float2 vab = *(const float2*)(vp + (size_t)t * C);         // LDG.64
        const float2 vcd = *(const float2*)(vp + (size_t)t * C + 2);
        const float2 vef = *(const float2*)(vp + (size_t)t * C + 4);
        const u64 vdup[6] = { dup_f32(vab.x), dup_f32(vab.y),
                              dup_f32(vcd.x), dup_f32(vcd.y),
                              dup_f32(vef.x), dup_f32(vef.y) };
        const u64 wa[2] = { W0.x, W0.y };
        const u64 wb[2] = { W1.x, W1.y };
#pragma unroll
        for (int jp = 0; jp < 2; ++jp)
#pragma unroll
            for (int kx = 0; kx < 6; ++kx) {
                ffma2(acc0[jp][kx], wa[jp], vdup[kx]);
                ffma2(acc1[jp][kx], wb[jp], vdup[kx]);
            }
    }

    // ---- Epilogue: level 3 ----
    float* ob  = out + (size_t)b * STR;
    float* o30 = ob + OFF3 + (size_t)i0 * LVL2;
    float* o31 = ob + OFF3 + (size_t)i1 * LVL2;
#pragma unroll
    for (int jp = 0; jp < 2; ++jp) {
        float lo0[6], hi0[6], lo1[6], hi1[6];
#pragma unroll
        for (int kx = 0; kx < 6; ++kx) {
            const float2 a = unpk(acc0[jp][kx]); lo0[kx] = a.x; hi0[kx] = a.y;
            const float2 c = unpk(acc1[jp][kx]); lo1[kx] = c.x; hi1[kx] = c.y;
        }
        const int jlo = j0 + 2 * jp, jhi = jlo + 1;
#pragma unroll
        for (int kp = 0; kp < 3; ++kp) {
            *(float2*)&o30[jlo * C + k0 + 2 * kp] = make_float2(lo0[2*kp], lo0[2*kp+1]);
            *(float2*)&o30[jhi * C + k0 + 2 * kp] = make_float2(hi0[2*kp], hi0[2*kp+1]);
            *(float2*)&o31[jlo * C + k0 + 2 * kp] = make_float2(lo1[2*kp], lo1[2*kp+1]);
            *(float2*)&o31[jhi * C + k0 + 2 * kp] = make_float2(hi1[2*kp], hi1[2*kp+1]);
        }
    }
}

extern "C" void kernel_launch(void* const* d_in, const int* in_sizes, int n_in,
                              void* d_out, int out_size)
{
    (void)in_sizes; (void)n_in; (void)out_size;
    const float* path = (const float*)d_in[0];
    float* out = (float*)d_out;

    dim3 g1(6, NB), b1(48, 8);       // (i-octet, batch), 384 thr
    sig_phase_a<<<g1, b1>>>(path, out);

    dim3 g2(C / 2, NB), b2(96);      // (i-pair, batch), 96 thr
    sig_phase_b<<<g2, b2>>>(out);
}